// round 12
// baseline (speedup 1.0000x reference)
#include <cuda_runtime.h>

// UpsampleLayer2D: x[B,R,C,64] -> out[B,2R,2C,16]
// out[b, ro, co, c] = x[b, ro%R, co%C, 4c + q],  q = 2*(ro>=R) + (co>=C)
//
// R12: champion warp-level layout, TPB=1024, 2 items/thread -> grid 2500.
// Evidence: harness-vs-ncu overhead shrinks with grid size (20000:+7.5us,
// 10000:+7.0, 5000:+3.1..4.4). Halve grid again while keeping the proven
// warp access pattern byte-identical:
//   thread handles items i and i+1024 within its block's 2048-item span;
//   read : 4 front-batched LDG.128 per item (8 total, MLP=8, proven safe)
//          -> warp reads 2KB fully contiguous per item group.
//   write: per quadrant one lane-contiguous STG.128 -> 512B contiguous
//          per warp per quadrant stream, full 128B lines (no RFO).

#define B_  32
#define R_  200
#define C_  200
#define NPIX    (B_ * R_ * C_)       // 1,280,000
#define NGROUPS (NPIX * 4)           // 5,120,000 (pixel,role) items
#define TPB     1024
#define IPT     2
#define GRID    (NGROUPS / (TPB * IPT))   // 2500, exact

__device__ __forceinline__ float comp(const float4& v, int q) {
    switch (q) {
        case 0:  return v.x;
        case 1:  return v.y;
        case 2:  return v.z;
        default: return v.w;
    }
}

__device__ __forceinline__ void scatter(unsigned idx, const float4 v[4],
                                        float4* __restrict__ op) {
    const unsigned t   = idx & 3u;
    const unsigned pix = idx >> 2;
    const unsigned col = pix % C_;
    const unsigned tmp = pix / C_;
    const unsigned row = tmp % R_;
    const unsigned b   = tmp / R_;

    #pragma unroll
    for (int q = 0; q < 4; q++) {
        const unsigned ro = row + R_ * (q >> 1);
        const unsigned co = col + C_ * (q & 1);
        const unsigned obase = ((b * (2u * R_) + ro) * (2u * C_) + co) * 4u + t;
        float4 w;
        w.x = comp(v[0], q);
        w.y = comp(v[1], q);
        w.z = comp(v[2], q);
        w.w = comp(v[3], q);
        op[obase] = w;
    }
}

__global__ __launch_bounds__(TPB)
void upsample_kernel(const float* __restrict__ in, float* __restrict__ out) {
    const unsigned base = blockIdx.x * (TPB * IPT) + threadIdx.x;
    const unsigned i0 = base;            // items base and base+TPB, both < NGROUPS
    const unsigned i1 = base + TPB;

    const float4* __restrict__ ibase = reinterpret_cast<const float4*>(in);
    float4* __restrict__ op = reinterpret_cast<float4*>(out);

    const float4* ip0 = ibase + (i0 >> 2) * 16u + (i0 & 3u) * 4u;
    const float4* ip1 = ibase + (i1 >> 2) * 16u + (i1 & 3u) * 4u;

    // Front-batch all 8 LDG.128.
    float4 a[4], b[4];
    a[0] = ip0[0];  a[1] = ip0[1];  a[2] = ip0[2];  a[3] = ip0[3];
    b[0] = ip1[0];  b[1] = ip1[1];  b[2] = ip1[2];  b[3] = ip1[3];

    scatter(i0, a, op);
    scatter(i1, b, op);
}

extern "C" void kernel_launch(void* const* d_in, const int* in_sizes, int n_in,
                              void* d_out, int out_size) {
    const float* x = (const float*)d_in[0];
    float* out = (float*)d_out;
    upsample_kernel<<<GRID, TPB>>>(x, out);
}

// round 13
// speedup vs baseline: 1.1116x; 1.1116x over previous
#include <cuda_runtime.h>

// UpsampleLayer2D: x[B,R,C,64] -> out[B,2R,2C,16]
// out[b, ro, co, c] = x[b, ro%R, co%C, 4c + q],  q = 2*(ro>=R) + (co>=C)
//
// FINAL (= R9/R11, harness-best 96.6us): champion warp layout, TPB=1024,
// one (pixel,role) item per thread.
//   read : channels [16t,16t+16) as 4 front-batched LDG.128
//          -> warp reads 2KB fully contiguous, sector-perfect.
//   write: per quadrant one lane-contiguous STG.128 -> warp writes 512B
//          contiguous per quadrant stream, full 128B lines (no RFO).
//
// 12-round record: pinned at the practical HBM3e ceiling (~83% DRAM-active,
// 6.6 TB/s, 655MB irreducible single-touch traffic). Probed and rejected:
// MLP x2 (neutral), MLP x2 in-CTA (-11%, L1tex queue), 256-bit v8 ops
// (-21%), half-pixel lanes (-19%), row-aligned 800-thr blocks (-3%),
// persistent grid-stride (-12%), cache hints (neutral), TPB 256/512/1024
// (flat). No further lever exists for a zero-reuse permutation.

#define B_  32
#define R_  200
#define C_  200
#define NPIX    (B_ * R_ * C_)       // 1,280,000
#define NGROUPS (NPIX * 4)           // 5,120,000 (pixel,role) items
#define TPB     1024
#define GRID    (NGROUPS / TPB)      // 5000, exact

__device__ __forceinline__ float comp(const float4& v, int q) {
    switch (q) {
        case 0:  return v.x;
        case 1:  return v.y;
        case 2:  return v.z;
        default: return v.w;
    }
}

__global__ __launch_bounds__(TPB)
void upsample_kernel(const float* __restrict__ in, float* __restrict__ out) {
    const unsigned idx = blockIdx.x * TPB + threadIdx.x;   // < NGROUPS, exact

    const unsigned t   = idx & 3u;      // role: input channels [16t, 16t+16)
    const unsigned pix = idx >> 2;

    const unsigned col = pix % C_;
    const unsigned tmp = pix / C_;
    const unsigned row = tmp % R_;
    const unsigned b   = tmp / R_;

    // Contiguous 64B read: channels [16t, 16t+16), front-batched.
    const float4* ip = reinterpret_cast<const float4*>(in) + pix * 16u + t * 4u;
    float4 v0 = ip[0];
    float4 v1 = ip[1];
    float4 v2 = ip[2];
    float4 v3 = ip[3];

    float4* op = reinterpret_cast<float4*>(out);

    #pragma unroll
    for (int q = 0; q < 4; q++) {
        const unsigned ro = row + R_ * (q >> 1);
        const unsigned co = col + C_ * (q & 1);
        const unsigned obase = ((b * (2u * R_) + ro) * (2u * C_) + co) * 4u + t;
        float4 w;
        w.x = comp(v0, q);
        w.y = comp(v1, q);
        w.z = comp(v2, q);
        w.w = comp(v3, q);
        op[obase] = w;
    }
}

extern "C" void kernel_launch(void* const* d_in, const int* in_sizes, int n_in,
                              void* d_out, int out_size) {
    const float* x = (const float*)d_in[0];
    float* out = (float*)d_out;
    upsample_kernel<<<GRID, TPB>>>(x, out);
}

// round 14
// speedup vs baseline: 1.1149x; 1.0030x over previous
#include <cuda_runtime.h>

// UpsampleLayer2D: x[B,R,C,64] -> out[B,2R,2C,16]
// out[b, ro, co, c] = x[b, ro%R, co%C, 4c + q],  q = 2*(ro>=R) + (co>=C)
//
// FINAL champion (harness-best 96.6us; dist {96.6, 97.8, 97.9}us over 4 runs).
// TPB=1024, one (pixel,role) item per thread, 4 threads per input pixel:
//   read : channels [16t,16t+16) as 4 front-batched LDG.128
//          -> warp reads 2KB fully contiguous, sector-perfect.
//   write: per quadrant one lane-contiguous STG.128 -> warp writes 512B
//          contiguous per quadrant stream, full 128B lines (no RFO).
//
// Pinned at the practical HBM3e ceiling: ~83% dram__cycles_active,
// 6.5-6.6 TB/s on 655MB irreducible single-touch traffic. 13-round probe
// record — rejected: 256-bit v8 ops (-21%), broken store contiguity (-19%),
// in-CTA MLP x8 (-11%), persistence (-12%), fat row blocks (-3%);
// flat: cross-grid MLP x8, cache hints, occupancy 29-88%, TPB 256/512/1024,
// grid 2500-20000. Zero-reuse permutation: no traffic reduction exists.

#define B_  32
#define R_  200
#define C_  200
#define NPIX    (B_ * R_ * C_)       // 1,280,000
#define NGROUPS (NPIX * 4)           // 5,120,000 (pixel,role) items
#define TPB     1024
#define GRID    (NGROUPS / TPB)      // 5000, exact

__device__ __forceinline__ float comp(const float4& v, int q) {
    switch (q) {
        case 0:  return v.x;
        case 1:  return v.y;
        case 2:  return v.z;
        default: return v.w;
    }
}

__global__ __launch_bounds__(TPB)
void upsample_kernel(const float* __restrict__ in, float* __restrict__ out) {
    const unsigned idx = blockIdx.x * TPB + threadIdx.x;   // < NGROUPS, exact

    const unsigned t   = idx & 3u;      // role: input channels [16t, 16t+16)
    const unsigned pix = idx >> 2;

    const unsigned col = pix % C_;
    const unsigned tmp = pix / C_;
    const unsigned row = tmp % R_;
    const unsigned b   = tmp / R_;

    // Contiguous 64B read: channels [16t, 16t+16), front-batched.
    const float4* ip = reinterpret_cast<const float4*>(in) + pix * 16u + t * 4u;
    float4 v0 = ip[0];
    float4 v1 = ip[1];
    float4 v2 = ip[2];
    float4 v3 = ip[3];

    float4* op = reinterpret_cast<float4*>(out);

    #pragma unroll
    for (int q = 0; q < 4; q++) {
        const unsigned ro = row + R_ * (q >> 1);
        const unsigned co = col + C_ * (q & 1);
        const unsigned obase = ((b * (2u * R_) + ro) * (2u * C_) + co) * 4u + t;
        float4 w;
        w.x = comp(v0, q);
        w.y = comp(v1, q);
        w.z = comp(v2, q);
        w.w = comp(v3, q);
        op[obase] = w;
    }
}

extern "C" void kernel_launch(void* const* d_in, const int* in_sizes, int n_in,
                              void* d_out, int out_size) {
    const float* x = (const float*)d_in[0];
    float* out = (float*)d_out;
    upsample_kernel<<<GRID, TPB>>>(x, out);
}

// round 15
// speedup vs baseline: 1.1237x; 1.0079x over previous
#include <cuda_runtime.h>

// UpsampleLayer2D: x[B,R,C,64] -> out[B,2R,2C,16]
// out[b, ro, co, c] = x[b, ro%R, co%C, 4c + q],  q = 2*(ro>=R) + (co>=C)
//
// FINAL champion (harness dist {96.6, 97.5, 97.8, 97.9}us over 5 runs).
// TPB=1024, one (pixel,role) item per thread, 4 threads per input pixel:
//   read : channels [16t,16t+16) as 4 front-batched LDG.128
//          -> warp reads 2KB fully contiguous, sector-perfect.
//   write: per quadrant one lane-contiguous STG.128 -> warp writes 512B
//          contiguous per quadrant stream, full 128B lines (no RFO).
//
// Pinned at the practical HBM3e ceiling: 81-84% dram__cycles_active,
// 6.45-6.63 TB/s on 655MB irreducible single-touch traffic. Probe record
// (14 rounds) — rejected: 256-bit v8 ops (-21%), broken store contiguity
// (-19%), in-CTA MLP x8 (-11%), persistence (-12%), fat row blocks (-3%);
// flat: cross-grid MLP x8, cache hints, occupancy 29-88%, TPB 256/512/1024,
// grid 2500-20000. TMA ruled out (LTS cap path-independent); zero reuse
// means no multicast or fusion opportunity. Terminal.

#define B_  32
#define R_  200
#define C_  200
#define NPIX    (B_ * R_ * C_)       // 1,280,000
#define NGROUPS (NPIX * 4)           // 5,120,000 (pixel,role) items
#define TPB     1024
#define GRID    (NGROUPS / TPB)      // 5000, exact

__device__ __forceinline__ float comp(const float4& v, int q) {
    switch (q) {
        case 0:  return v.x;
        case 1:  return v.y;
        case 2:  return v.z;
        default: return v.w;
    }
}

__global__ __launch_bounds__(TPB)
void upsample_kernel(const float* __restrict__ in, float* __restrict__ out) {
    const unsigned idx = blockIdx.x * TPB + threadIdx.x;   // < NGROUPS, exact

    const unsigned t   = idx & 3u;      // role: input channels [16t, 16t+16)
    const unsigned pix = idx >> 2;

    const unsigned col = pix % C_;
    const unsigned tmp = pix / C_;
    const unsigned row = tmp % R_;
    const unsigned b   = tmp / R_;

    // Contiguous 64B read: channels [16t, 16t+16), front-batched.
    const float4* ip = reinterpret_cast<const float4*>(in) + pix * 16u + t * 4u;
    float4 v0 = ip[0];
    float4 v1 = ip[1];
    float4 v2 = ip[2];
    float4 v3 = ip[3];

    float4* op = reinterpret_cast<float4*>(out);

    #pragma unroll
    for (int q = 0; q < 4; q++) {
        const unsigned ro = row + R_ * (q >> 1);
        const unsigned co = col + C_ * (q & 1);
        const unsigned obase = ((b * (2u * R_) + ro) * (2u * C_) + co) * 4u + t;
        float4 w;
        w.x = comp(v0, q);
        w.y = comp(v1, q);
        w.z = comp(v2, q);
        w.w = comp(v3, q);
        op[obase] = w;
    }
}

extern "C" void kernel_launch(void* const* d_in, const int* in_sizes, int n_in,
                              void* d_out, int out_size) {
    const float* x = (const float*)d_in[0];
    float* out = (float*)d_out;
    upsample_kernel<<<GRID, TPB>>>(x, out);
}